// round 13
// baseline (speedup 1.0000x reference)
#include <cuda_runtime.h>
#include <cstdint>

// ClusteringLayer: per-64-element-line greedy clustering, threshold 0.1f.
// Bases pairwise >= 0.1 apart => <=1 base per 0.1-wide RN bucket; matches
// confined to buckets k-1..k+1. Table entries are PRE-ROTATED ror6 of
// {val rounded to 64 ulp | 6-bit order}: ord sits in the MSBs so a plain
// unsigned min picks the earliest matching base with no per-probe shift.
// Quad-speculative resolve; cp.async.cg double-buffered stage-in;
// st.global.cs streaming stage-out. Empty = ror6(qNaN) (compare false).

#define THREADS   576           // 18 warps
#define WARPS     18
#define THRESH    0.1f
#define SROT      0x01FF0000u   // ror6(0x7FC00000 qNaN)

// RN bucket magic: fb = RN(x*10 + 2^23 + 32); k = low mantissa bits in [1,62]
#define BMAGIC    8388640.0f
#define BLO       8388609.0f
#define BHI       8388670.0f

// per-warp smem (bytes):
//   [0,     8192)  vals: u32[64][32] rotated entries   (bank==lane, CF)
//   [8192,  10240) stgA: float4[32 lines][1 quarter], swizzled
//   [10240, 12288) stgB: second buffer
#define STGA_OFF   8192
#define STGB_OFF   10240
#define WARP_BYTES 12288
#define SMEM_TOTAL (WARP_BYTES * WARPS)     // 221184

extern __shared__ char smem_dyn[];

__device__ __forceinline__ int bucket_idx(float xi) {
    float fb = fmaf(xi, 10.0f, BMAGIC);
    fb = fminf(fmaxf(fb, BLO), BHI);
    return __float_as_int(fb) & 63;          // 1..62
}
__device__ __forceinline__ unsigned rol6(unsigned v) {
    return __funnelshift_l(v, v, 6);
}
__device__ __forceinline__ unsigned ror6(unsigned v) {
    return __funnelshift_r(v, v, 6);
}
// rotated new entry for (xi, e)
__device__ __forceinline__ unsigned rpack(float xi, int e) {
    return ror6(((__float_as_uint(xi) + 32u) & ~63u) | (unsigned)e);
}
// 3-bucket probe: min of rotated entries that match xi
__device__ __forceinline__ unsigned probe3(const unsigned* vals, int vi, float xi) {
    unsigned mk = 0xFFFFFFFFu;
    unsigned ev;
    ev = vals[vi - 32];
    if (fabsf(__uint_as_float(rol6(ev)) - xi) < THRESH) mk = min(mk, ev);
    ev = vals[vi];
    if (fabsf(__uint_as_float(rol6(ev)) - xi) < THRESH) mk = min(mk, ev);
    ev = vals[vi + 32];
    if (fabsf(__uint_as_float(rol6(ev)) - xi) < THRESH) mk = min(mk, ev);
    return mk;
}
__device__ __forceinline__ void stg_cs(float4* p, float4 v) {
    asm volatile("st.global.cs.v4.f32 [%0], {%1,%2,%3,%4};"
                 :: "l"(p), "f"(v.x), "f"(v.y), "f"(v.z), "f"(v.w) : "memory");
}

// async-copy one quarter (4 x 16B per thread) into a staging buffer
__device__ __forceinline__ void issue_quarter(float4* dstbuf, const float4* gin,
                                              int h, int nvalid, int lane) {
    #pragma unroll
    for (int c = 0; c < 4; c++) {
        const int idx = c * 32 + lane;
        const int l   = idx >> 2;
        const int q   = idx & 3;
        if (l < nvalid) {
            const uint32_t dst = (uint32_t)__cvta_generic_to_shared(
                dstbuf + l * 4 + (q ^ ((l >> 1) & 3)));
            asm volatile("cp.async.cg.shared.global [%0], [%1], 16;"
                         :: "r"(dst), "l"(gin + l * 16 + 4 * h + q));
        }
    }
    asm volatile("cp.async.commit_group;");
}

template <bool FULL>
__device__ __forceinline__ void process_and_flush(
    unsigned* vals, float4* stg4, float4* gout,
    int h, int nvalid, int lane, int lsw2)
{
    if (FULL || lane < nvalid) {
        #pragma unroll
        for (int qi = 0; qi < 4; qi++) {
            const int sidx = lane * 4 + (qi ^ lsw2);
            float4 xv = stg4[sidx];
            const float x0 = xv.x, x1 = xv.y, x2 = xv.z, x3 = xv.w;
            const int e0 = 16 * h + 4 * qi;

            const int vi0 = bucket_idx(x0) * 32 + lane;
            const int vi1 = bucket_idx(x1) * 32 + lane;
            const int vi2 = bucket_idx(x2) * 32 + lane;
            const int vi3 = bucket_idx(x3) * 32 + lane;

            // 12 probes on pre-quad state (LDS latency overlapped)
            const unsigned mk0 = probe3(vals, vi0, x0);
            const unsigned mk1 = probe3(vals, vi1, x1);
            const unsigned mk2 = probe3(vals, vi2, x2);
            const unsigned mk3 = probe3(vals, vi3, x3);

            // register-only resolve with cross-candidates
            const bool f0 = (mk0 != 0xFFFFFFFFu);
            const unsigned ro0 = rpack(x0, e0);
            const unsigned r0m = f0 ? 0xFFFFFFFFu : ro0;

            unsigned m1 = min(mk1,
                (fabsf(x0 - x1) < THRESH) ? r0m : 0xFFFFFFFFu);
            const bool f1 = (m1 != 0xFFFFFFFFu);
            const unsigned ro1 = rpack(x1, e0 + 1);
            const unsigned r1m = f1 ? 0xFFFFFFFFu : ro1;

            unsigned m2 = min(min(mk2,
                (fabsf(x0 - x2) < THRESH) ? r0m : 0xFFFFFFFFu),
                (fabsf(x1 - x2) < THRESH) ? r1m : 0xFFFFFFFFu);
            const bool f2 = (m2 != 0xFFFFFFFFu);
            const unsigned ro2 = rpack(x2, e0 + 2);
            const unsigned r2m = f2 ? 0xFFFFFFFFu : ro2;

            unsigned m3 = min(min(min(mk3,
                (fabsf(x0 - x3) < THRESH) ? r0m : 0xFFFFFFFFu),
                (fabsf(x1 - x3) < THRESH) ? r1m : 0xFFFFFFFFu),
                (fabsf(x2 - x3) < THRESH) ? r2m : 0xFFFFFFFFu);
            const bool f3 = (m3 != 0xFFFFFFFFu);
            const unsigned ro3 = rpack(x3, e0 + 3);

            float4 ov;
            ov.x = f0 ? __uint_as_float(rol6(mk0)) : x0;
            ov.y = f1 ? __uint_as_float(rol6(m1))  : x1;
            ov.z = f2 ? __uint_as_float(rol6(m2))  : x2;
            ov.w = f3 ? __uint_as_float(rol6(m3))  : x3;
            stg4[sidx] = ov;

            // predicated inserts (distinct buckets guaranteed within quad)
            if (!f0) vals[vi0] = ro0;
            if (!f1) vals[vi1] = ro1;
            if (!f2) vals[vi2] = ro2;
            if (!f3) vals[vi3] = ro3;
        }
    }
    __syncwarp();

    // stage out: swizzled LDS.128 (CF), coalesced streaming STG.128
    #pragma unroll
    for (int c = 0; c < 4; c++) {
        const int idx = c * 32 + lane;
        const int l   = idx >> 2;
        const int q   = idx & 3;
        if (FULL || l < nvalid)
            stg_cs(gout + l * 16 + 4 * h + q,
                   stg4[l * 4 + (q ^ ((l >> 1) & 3))]);
    }
    __syncwarp();   // all lanes done with this buffer before it refills
}

__global__ void __launch_bounds__(THREADS, 1)
cluster_kernel(const float* __restrict__ x, float* __restrict__ out, long n)
{
    const int tid  = threadIdx.x;
    const int wid  = tid >> 5;
    const int lane = tid & 31;

    char*     wbase = smem_dyn + (long)wid * WARP_BYTES;
    unsigned* vals  = (unsigned*)wbase;
    float4*   bufs[2] = { (float4*)(wbase + STGA_OFF),
                          (float4*)(wbase + STGB_OFF) };

    const uint4 sent4 = make_uint4(SROT, SROT, SROT, SROT);
    {
        uint4* vp = (uint4*)vals;
        #pragma unroll
        for (int j = 0; j < 16; j++) vp[j * 32 + lane] = sent4;
    }
    __syncwarp();

    const long n_lines = n >> 6;

    // tail copy (n % 64; zero for this shape, kept for generality)
    {
        const long tail0 = n_lines << 6;
        for (long t = (long)blockIdx.x * blockDim.x + tid + tail0; t < n;
             t += (long)gridDim.x * blockDim.x)
            out[t] = x[t];
    }

    const long n_batches = (n_lines + 31) >> 5;
    const long gwarp = (long)blockIdx.x * WARPS + wid;
    const long nwarp = (long)gridDim.x * WARPS;
    const int  lsw2  = (lane >> 1) & 3;

    int cur = 0;

    // prologue: start quarter 0 of first batch
    if (gwarp < n_batches) {
        const long line0 = gwarp << 5;
        long nv_l = n_lines - line0;
        const int nv = (nv_l >= 32) ? 32 : (int)nv_l;
        issue_quarter(bufs[0], (const float4*)x + (line0 << 4), 0, nv, lane);
    }

    for (long b = gwarp; b < n_batches; b += nwarp) {
        const long line0 = b << 5;
        const float4* gin  = (const float4*)x   + (line0 << 4);
        float4*       gout = (float4*)out       + (line0 << 4);
        long nv_l = n_lines - line0;
        const int nvalid = (nv_l >= 32) ? 32 : (int)nv_l;

        #pragma unroll
        for (int h = 0; h < 4; h++) {
            // issue next quarter into the other buffer, then wait for current
            if (h < 3) {
                issue_quarter(bufs[cur ^ 1], gin, h + 1, nvalid, lane);
                asm volatile("cp.async.wait_group 1;");
            } else {
                const long bn = b + nwarp;
                if (bn < n_batches) {
                    const long l0n = bn << 5;
                    long nvn_l = n_lines - l0n;
                    const int nvn = (nvn_l >= 32) ? 32 : (int)nvn_l;
                    issue_quarter(bufs[cur ^ 1],
                                  (const float4*)x + (l0n << 4), 0, nvn, lane);
                    asm volatile("cp.async.wait_group 1;");
                } else {
                    asm volatile("cp.async.wait_group 0;");
                }
            }
            __syncwarp();

            if (nvalid == 32)
                process_and_flush<true >(vals, bufs[cur], gout, h, 32,     lane, lsw2);
            else
                process_and_flush<false>(vals, bufs[cur], gout, h, nvalid, lane, lsw2);

            cur ^= 1;
        }

        // bulk cleanup: wipe table to sentinel (coalesced STS.128)
        {
            uint4* vp = (uint4*)vals;
            #pragma unroll
            for (int j = 0; j < 16; j++) vp[j * 32 + lane] = sent4;
        }
        __syncwarp();
    }
}

extern "C" void kernel_launch(void* const* d_in, const int* in_sizes, int n_in,
                              void* d_out, int out_size)
{
    (void)n_in; (void)out_size;
    const float* x = (const float*)d_in[0];
    float* out = (float*)d_out;
    const long n = (long)in_sizes[0];

    cudaFuncSetAttribute(cluster_kernel,
                         cudaFuncAttributeMaxDynamicSharedMemorySize, SMEM_TOTAL);

    cluster_kernel<<<148, THREADS, SMEM_TOTAL>>>(x, out, n);
}

// round 14
// speedup vs baseline: 1.0214x; 1.0214x over previous
#include <cuda_runtime.h>
#include <cstdint>

// ClusteringLayer: per-64-element-line greedy clustering, threshold 0.1f.
// Bases pairwise >= 0.1 apart => <=1 base per 0.1-wide RN bucket; matches
// confined to buckets k-1..k+1. Table entry = {val rounded to 64 ulp, 6-bit
// appearance order} in one u32; candidate eval ror6 (ord->MSBs) + umin.
// Quad-speculative resolve (12 probes up front, register cross-candidates).
// cp.async.cg double-buffered stage-in (R12). R14 adds ONLY: streaming
// st.global.cs stage-out + full-batch template specialization. Hot loop is
// byte-identical to R12 (its compiled form measured best: 61 regs, 73% issue).

#define THREADS   576           // 18 warps
#define WARPS     18
#define THRESH    0.1f
#define SENTV     0x7FC00000u   // qNaN

// RN bucket magic: fb = RN(x*10 + 2^23 + 32); k = low mantissa bits in [1,62]
#define BMAGIC    8388640.0f
#define BLO       8388609.0f
#define BHI       8388670.0f

// per-warp smem (bytes):
//   [0,     8192)  vals: u32[64][32] packed {val|ord}   (bank==lane, CF)
//   [8192,  10240) stgA: float4[32 lines][1 quarter], swizzled
//   [10240, 12288) stgB: second buffer (double buffering)
#define STGA_OFF   8192
#define STGB_OFF   10240
#define WARP_BYTES 12288
#define SMEM_TOTAL (WARP_BYTES * WARPS)     // 221184

extern __shared__ char smem_dyn[];

__device__ __forceinline__ int bucket_idx(float xi) {
    float fb = fmaf(xi, 10.0f, BMAGIC);
    fb = fminf(fmaxf(fb, BLO), BHI);
    return __float_as_int(fb) & 63;          // 1..62
}
__device__ __forceinline__ unsigned cand(unsigned ev, float xi) {
    return (fabsf(__uint_as_float(ev) - xi) < THRESH)
               ? __funnelshift_r(ev, ev, 6) : 0xFFFFFFFFu;
}
__device__ __forceinline__ unsigned packv(float xi, int e) {
    return ((__float_as_uint(xi) + 32u) & ~63u) | (unsigned)e;
}
__device__ __forceinline__ void stg_cs(float4* p, float4 v) {
    asm volatile("st.global.cs.v4.f32 [%0], {%1,%2,%3,%4};"
                 :: "l"(p), "f"(v.x), "f"(v.y), "f"(v.z), "f"(v.w) : "memory");
}

// async-copy one quarter (4 x 16B per thread) into a staging buffer
template <bool FULL>
__device__ __forceinline__ void issue_quarter(float4* dstbuf, const float4* gin,
                                              int h, int nvalid, int lane) {
    #pragma unroll
    for (int c = 0; c < 4; c++) {
        const int idx = c * 32 + lane;
        const int l   = idx >> 2;
        const int q   = idx & 3;
        if (FULL || l < nvalid) {
            const uint32_t dst = (uint32_t)__cvta_generic_to_shared(
                dstbuf + l * 4 + (q ^ ((l >> 1) & 3)));
            asm volatile("cp.async.cg.shared.global [%0], [%1], 16;"
                         :: "r"(dst), "l"(gin + l * 16 + 4 * h + q));
        }
    }
    asm volatile("cp.async.commit_group;");
}

// process one 16-element quarter + streaming stage-out (hot loop == R12)
template <bool FULL>
__device__ __forceinline__ void process_and_flush(
    unsigned* vals, float4* stg4, float4* gout,
    int h, int nvalid, int lane, int lsw2)
{
    if (FULL || lane < nvalid) {
        #pragma unroll 1
        for (int qi = 0; qi < 4; qi++) {
            const int sidx = lane * 4 + (qi ^ lsw2);
            float4 xv = stg4[sidx];
            const float x0 = xv.x, x1 = xv.y, x2 = xv.z, x3 = xv.w;
            const int e0 = 16 * h + 4 * qi;

            const int vi0 = bucket_idx(x0) * 32 + lane;
            const int vi1 = bucket_idx(x1) * 32 + lane;
            const int vi2 = bucket_idx(x2) * 32 + lane;
            const int vi3 = bucket_idx(x3) * 32 + lane;

            // 12 probes on pre-quad state (latency overlapped)
            const unsigned mk0 = min(min(cand(vals[vi0-32], x0),
                                         cand(vals[vi0   ], x0)),
                                         cand(vals[vi0+32], x0));
            const unsigned mk1 = min(min(cand(vals[vi1-32], x1),
                                         cand(vals[vi1   ], x1)),
                                         cand(vals[vi1+32], x1));
            const unsigned mk2 = min(min(cand(vals[vi2-32], x2),
                                         cand(vals[vi2   ], x2)),
                                         cand(vals[vi2+32], x2));
            const unsigned mk3 = min(min(cand(vals[vi3-32], x3),
                                         cand(vals[vi3   ], x3)),
                                         cand(vals[vi3+32], x3));

            // register-only resolve with cross-candidates
            const bool f0 = (mk0 != 0xFFFFFFFFu);
            const unsigned ne0 = packv(x0, e0);
            const unsigned r0  = __funnelshift_r(ne0, ne0, 6);

            const unsigned c01 = (!f0 && fabsf(x0 - x1) < THRESH)
                                     ? r0 : 0xFFFFFFFFu;
            const unsigned m1  = min(mk1, c01);
            const bool f1 = (m1 != 0xFFFFFFFFu);
            const unsigned ne1 = packv(x1, e0 + 1);
            const unsigned r1  = __funnelshift_r(ne1, ne1, 6);

            const unsigned c02 = (!f0 && fabsf(x0 - x2) < THRESH)
                                     ? r0 : 0xFFFFFFFFu;
            const unsigned c12 = (!f1 && fabsf(x1 - x2) < THRESH)
                                     ? r1 : 0xFFFFFFFFu;
            const unsigned m2  = min(min(mk2, c02), c12);
            const bool f2 = (m2 != 0xFFFFFFFFu);
            const unsigned ne2 = packv(x2, e0 + 2);
            const unsigned r2  = __funnelshift_r(ne2, ne2, 6);

            const unsigned c03 = (!f0 && fabsf(x0 - x3) < THRESH)
                                     ? r0 : 0xFFFFFFFFu;
            const unsigned c13 = (!f1 && fabsf(x1 - x3) < THRESH)
                                     ? r1 : 0xFFFFFFFFu;
            const unsigned c23 = (!f2 && fabsf(x2 - x3) < THRESH)
                                     ? r2 : 0xFFFFFFFFu;
            const unsigned m3  = min(min(min(mk3, c03), c13), c23);
            const bool f3 = (m3 != 0xFFFFFFFFu);
            const unsigned ne3 = packv(x3, e0 + 3);

            float4 ov;
            ov.x = f0 ? __uint_as_float(__funnelshift_l(mk0, mk0, 6)) : x0;
            ov.y = f1 ? __uint_as_float(__funnelshift_l(m1,  m1,  6)) : x1;
            ov.z = f2 ? __uint_as_float(__funnelshift_l(m2,  m2,  6)) : x2;
            ov.w = f3 ? __uint_as_float(__funnelshift_l(m3,  m3,  6)) : x3;
            stg4[sidx] = ov;

            // predicated inserts (distinct buckets guaranteed within quad)
            if (!f0) vals[vi0] = ne0;
            if (!f1) vals[vi1] = ne1;
            if (!f2) vals[vi2] = ne2;
            if (!f3) vals[vi3] = ne3;
        }
    }
    __syncwarp();

    // stage out: swizzled LDS.128 (CF), coalesced streaming STG.128
    #pragma unroll
    for (int c = 0; c < 4; c++) {
        const int idx = c * 32 + lane;
        const int l   = idx >> 2;
        const int q   = idx & 3;
        if (FULL || l < nvalid)
            stg_cs(gout + l * 16 + 4 * h + q,
                   stg4[l * 4 + (q ^ ((l >> 1) & 3))]);
    }
    __syncwarp();   // all lanes done with this buffer before it refills
}

__global__ void __launch_bounds__(THREADS, 1)
cluster_kernel(const float* __restrict__ x, float* __restrict__ out, long n)
{
    const int tid  = threadIdx.x;
    const int wid  = tid >> 5;
    const int lane = tid & 31;

    char*     wbase = smem_dyn + (long)wid * WARP_BYTES;
    unsigned* vals  = (unsigned*)wbase;
    float4*   bufs[2] = { (float4*)(wbase + STGA_OFF),
                          (float4*)(wbase + STGB_OFF) };

    const uint4 sent4 = make_uint4(SENTV, SENTV, SENTV, SENTV);
    {
        uint4* vp = (uint4*)vals;
        #pragma unroll
        for (int j = 0; j < 16; j++) vp[j * 32 + lane] = sent4;
    }
    __syncwarp();

    const long n_lines = n >> 6;

    // tail copy (n % 64; zero for this shape, kept for generality)
    {
        const long tail0 = n_lines << 6;
        for (long t = (long)blockIdx.x * blockDim.x + tid + tail0; t < n;
             t += (long)gridDim.x * blockDim.x)
            out[t] = x[t];
    }

    const long n_batches = (n_lines + 31) >> 5;
    const long gwarp = (long)blockIdx.x * WARPS + wid;
    const long nwarp = (long)gridDim.x * WARPS;
    const int  lsw2  = (lane >> 1) & 3;

    int cur = 0;

    // prologue: start quarter 0 of first batch
    if (gwarp < n_batches) {
        const long line0 = gwarp << 5;
        long nv_l = n_lines - line0;
        const int nv = (nv_l >= 32) ? 32 : (int)nv_l;
        if (nv == 32)
            issue_quarter<true >(bufs[0], (const float4*)x + (line0 << 4), 0, 32, lane);
        else
            issue_quarter<false>(bufs[0], (const float4*)x + (line0 << 4), 0, nv, lane);
    }

    for (long b = gwarp; b < n_batches; b += nwarp) {
        const long line0 = b << 5;
        const float4* gin  = (const float4*)x   + (line0 << 4);
        float4*       gout = (float4*)out       + (line0 << 4);
        long nv_l = n_lines - line0;
        const int nvalid = (nv_l >= 32) ? 32 : (int)nv_l;
        const bool full = (nvalid == 32);

        #pragma unroll
        for (int h = 0; h < 4; h++) {
            // issue next quarter into the other buffer, then wait for current
            if (h < 3) {
                if (full) issue_quarter<true >(bufs[cur ^ 1], gin, h + 1, 32,     lane);
                else      issue_quarter<false>(bufs[cur ^ 1], gin, h + 1, nvalid, lane);
                asm volatile("cp.async.wait_group 1;");
            } else {
                const long bn = b + nwarp;
                if (bn < n_batches) {
                    const long l0n = bn << 5;
                    long nvn_l = n_lines - l0n;
                    const int nvn = (nvn_l >= 32) ? 32 : (int)nvn_l;
                    if (nvn == 32)
                        issue_quarter<true >(bufs[cur ^ 1],
                                             (const float4*)x + (l0n << 4), 0, 32, lane);
                    else
                        issue_quarter<false>(bufs[cur ^ 1],
                                             (const float4*)x + (l0n << 4), 0, nvn, lane);
                    asm volatile("cp.async.wait_group 1;");
                } else {
                    asm volatile("cp.async.wait_group 0;");
                }
            }
            __syncwarp();

            if (full)
                process_and_flush<true >(vals, bufs[cur], gout, h, 32,     lane, lsw2);
            else
                process_and_flush<false>(vals, bufs[cur], gout, h, nvalid, lane, lsw2);

            cur ^= 1;
        }

        // bulk cleanup: wipe table to sentinel (coalesced STS.128)
        {
            uint4* vp = (uint4*)vals;
            #pragma unroll
            for (int j = 0; j < 16; j++) vp[j * 32 + lane] = sent4;
        }
        __syncwarp();
    }
}

extern "C" void kernel_launch(void* const* d_in, const int* in_sizes, int n_in,
                              void* d_out, int out_size)
{
    (void)n_in; (void)out_size;
    const float* x = (const float*)d_in[0];
    float* out = (float*)d_out;
    const long n = (long)in_sizes[0];

    cudaFuncSetAttribute(cluster_kernel,
                         cudaFuncAttributeMaxDynamicSharedMemorySize, SMEM_TOTAL);

    cluster_kernel<<<148, THREADS, SMEM_TOTAL>>>(x, out, n);
}

// round 15
// speedup vs baseline: 1.0306x; 1.0091x over previous
#include <cuda_runtime.h>
#include <cstdint>

// ClusteringLayer: per-64-element-line greedy clustering, threshold 0.1f.
// Bases pairwise >= 0.1 apart => <=1 base per 0.1-wide RN bucket; matches
// confined to buckets k-1..k+1. Table entries are PRE-ROTATED ror6 of
// {val rounded to 64 ulp | 6-bit order}: ord in MSBs, so probes do a
// predicated unsigned min (no SEL, no per-insert re-rotation).
// Quad-speculative resolve; cp.async.cg double-buffered stage-in;
// st.global.cs streaming stage-out. Empty = ror6(qNaN) (compare false).
// Identical to R14 except the probe/insert encoding (single-change round).

#define THREADS   576           // 18 warps
#define WARPS     18
#define THRESH    0.1f
#define SROT      0x01FF0000u   // ror6(0x7FC00000 qNaN)

// RN bucket magic: fb = RN(x*10 + 2^23 + 32); k = low mantissa bits in [1,62]
#define BMAGIC    8388640.0f
#define BLO       8388609.0f
#define BHI       8388670.0f

// per-warp smem (bytes):
//   [0,     8192)  vals: u32[64][32] rotated entries   (bank==lane, CF)
//   [8192,  10240) stgA: float4[32 lines][1 quarter], swizzled
//   [10240, 12288) stgB: second buffer (double buffering)
#define STGA_OFF   8192
#define STGB_OFF   10240
#define WARP_BYTES 12288
#define SMEM_TOTAL (WARP_BYTES * WARPS)     // 221184

extern __shared__ char smem_dyn[];

__device__ __forceinline__ int bucket_idx(float xi) {
    float fb = fmaf(xi, 10.0f, BMAGIC);
    fb = fminf(fmaxf(fb, BLO), BHI);
    return __float_as_int(fb) & 63;          // 1..62
}
__device__ __forceinline__ unsigned rol6(unsigned v) {
    return __funnelshift_l(v, v, 6);
}
// rotated new entry for (xi, e): ord<<26 | rounded-val>>6
__device__ __forceinline__ unsigned rpack(float xi, int e) {
    const unsigned nv = (__float_as_uint(xi) + 32u) & ~63u;
    return __funnelshift_r(nv | (unsigned)e, nv | (unsigned)e, 6);
}
// predicated-min probe: mk = min(mk, entry) iff entry value matches xi
__device__ __forceinline__ void probe_min(unsigned& mk, const unsigned* vals,
                                          int vi, float xi) {
    const unsigned ev = vals[vi];
    const float v = __uint_as_float(rol6(ev));
    if (fabsf(v - xi) < THRESH) mk = min(mk, ev);
}
__device__ __forceinline__ void stg_cs(float4* p, float4 v) {
    asm volatile("st.global.cs.v4.f32 [%0], {%1,%2,%3,%4};"
                 :: "l"(p), "f"(v.x), "f"(v.y), "f"(v.z), "f"(v.w) : "memory");
}

// async-copy one quarter (4 x 16B per thread) into a staging buffer
template <bool FULL>
__device__ __forceinline__ void issue_quarter(float4* dstbuf, const float4* gin,
                                              int h, int nvalid, int lane) {
    #pragma unroll
    for (int c = 0; c < 4; c++) {
        const int idx = c * 32 + lane;
        const int l   = idx >> 2;
        const int q   = idx & 3;
        if (FULL || l < nvalid) {
            const uint32_t dst = (uint32_t)__cvta_generic_to_shared(
                dstbuf + l * 4 + (q ^ ((l >> 1) & 3)));
            asm volatile("cp.async.cg.shared.global [%0], [%1], 16;"
                         :: "r"(dst), "l"(gin + l * 16 + 4 * h + q));
        }
    }
    asm volatile("cp.async.commit_group;");
}

// process one 16-element quarter + streaming stage-out
template <bool FULL>
__device__ __forceinline__ void process_and_flush(
    unsigned* vals, float4* stg4, float4* gout,
    int h, int nvalid, int lane, int lsw2)
{
    if (FULL || lane < nvalid) {
        #pragma unroll 1
        for (int qi = 0; qi < 4; qi++) {
            const int sidx = lane * 4 + (qi ^ lsw2);
            float4 xv = stg4[sidx];
            const float x0 = xv.x, x1 = xv.y, x2 = xv.z, x3 = xv.w;
            const int e0 = 16 * h + 4 * qi;

            const int vi0 = bucket_idx(x0) * 32 + lane;
            const int vi1 = bucket_idx(x1) * 32 + lane;
            const int vi2 = bucket_idx(x2) * 32 + lane;
            const int vi3 = bucket_idx(x3) * 32 + lane;

            // 12 probes on pre-quad state (latency overlapped)
            unsigned mk0 = 0xFFFFFFFFu, mk1 = 0xFFFFFFFFu;
            unsigned mk2 = 0xFFFFFFFFu, mk3 = 0xFFFFFFFFu;
            probe_min(mk0, vals, vi0 - 32, x0);
            probe_min(mk0, vals, vi0,      x0);
            probe_min(mk0, vals, vi0 + 32, x0);
            probe_min(mk1, vals, vi1 - 32, x1);
            probe_min(mk1, vals, vi1,      x1);
            probe_min(mk1, vals, vi1 + 32, x1);
            probe_min(mk2, vals, vi2 - 32, x2);
            probe_min(mk2, vals, vi2,      x2);
            probe_min(mk2, vals, vi2 + 32, x2);
            probe_min(mk3, vals, vi3 - 32, x3);
            probe_min(mk3, vals, vi3,      x3);
            probe_min(mk3, vals, vi3 + 32, x3);

            // register-only resolve with cross-candidates (rotated domain)
            const bool f0 = (mk0 != 0xFFFFFFFFu);
            const unsigned ro0 = rpack(x0, e0);
            const unsigned r0m = f0 ? 0xFFFFFFFFu : ro0;

            const unsigned c01 = (fabsf(x0 - x1) < THRESH) ? r0m : 0xFFFFFFFFu;
            const unsigned m1  = min(mk1, c01);
            const bool f1 = (m1 != 0xFFFFFFFFu);
            const unsigned ro1 = rpack(x1, e0 + 1);
            const unsigned r1m = f1 ? 0xFFFFFFFFu : ro1;

            const unsigned c02 = (fabsf(x0 - x2) < THRESH) ? r0m : 0xFFFFFFFFu;
            const unsigned c12 = (fabsf(x1 - x2) < THRESH) ? r1m : 0xFFFFFFFFu;
            const unsigned m2  = min(min(mk2, c02), c12);
            const bool f2 = (m2 != 0xFFFFFFFFu);
            const unsigned ro2 = rpack(x2, e0 + 2);
            const unsigned r2m = f2 ? 0xFFFFFFFFu : ro2;

            const unsigned c03 = (fabsf(x0 - x3) < THRESH) ? r0m : 0xFFFFFFFFu;
            const unsigned c13 = (fabsf(x1 - x3) < THRESH) ? r1m : 0xFFFFFFFFu;
            const unsigned c23 = (fabsf(x2 - x3) < THRESH) ? r2m : 0xFFFFFFFFu;
            const unsigned m3  = min(min(min(mk3, c03), c13), c23);
            const bool f3 = (m3 != 0xFFFFFFFFu);
            const unsigned ro3 = rpack(x3, e0 + 3);

            float4 ov;
            ov.x = f0 ? __uint_as_float(rol6(mk0)) : x0;
            ov.y = f1 ? __uint_as_float(rol6(m1))  : x1;
            ov.z = f2 ? __uint_as_float(rol6(m2))  : x2;
            ov.w = f3 ? __uint_as_float(rol6(m3))  : x3;
            stg4[sidx] = ov;

            // predicated inserts (distinct buckets guaranteed within quad)
            if (!f0) vals[vi0] = ro0;
            if (!f1) vals[vi1] = ro1;
            if (!f2) vals[vi2] = ro2;
            if (!f3) vals[vi3] = ro3;
        }
    }
    __syncwarp();

    // stage out: swizzled LDS.128 (CF), coalesced streaming STG.128
    #pragma unroll
    for (int c = 0; c < 4; c++) {
        const int idx = c * 32 + lane;
        const int l   = idx >> 2;
        const int q   = idx & 3;
        if (FULL || l < nvalid)
            stg_cs(gout + l * 16 + 4 * h + q,
                   stg4[l * 4 + (q ^ ((l >> 1) & 3))]);
    }
    __syncwarp();   // all lanes done with this buffer before it refills
}

__global__ void __launch_bounds__(THREADS, 1)
cluster_kernel(const float* __restrict__ x, float* __restrict__ out, long n)
{
    const int tid  = threadIdx.x;
    const int wid  = tid >> 5;
    const int lane = tid & 31;

    char*     wbase = smem_dyn + (long)wid * WARP_BYTES;
    unsigned* vals  = (unsigned*)wbase;
    float4*   bufs[2] = { (float4*)(wbase + STGA_OFF),
                          (float4*)(wbase + STGB_OFF) };

    const uint4 sent4 = make_uint4(SROT, SROT, SROT, SROT);
    {
        uint4* vp = (uint4*)vals;
        #pragma unroll
        for (int j = 0; j < 16; j++) vp[j * 32 + lane] = sent4;
    }
    __syncwarp();

    const long n_lines = n >> 6;

    // tail copy (n % 64; zero for this shape, kept for generality)
    {
        const long tail0 = n_lines << 6;
        for (long t = (long)blockIdx.x * blockDim.x + tid + tail0; t < n;
             t += (long)gridDim.x * blockDim.x)
            out[t] = x[t];
    }

    const long n_batches = (n_lines + 31) >> 5;
    const long gwarp = (long)blockIdx.x * WARPS + wid;
    const long nwarp = (long)gridDim.x * WARPS;
    const int  lsw2  = (lane >> 1) & 3;

    int cur = 0;

    // prologue: start quarter 0 of first batch
    if (gwarp < n_batches) {
        const long line0 = gwarp << 5;
        long nv_l = n_lines - line0;
        const int nv = (nv_l >= 32) ? 32 : (int)nv_l;
        if (nv == 32)
            issue_quarter<true >(bufs[0], (const float4*)x + (line0 << 4), 0, 32, lane);
        else
            issue_quarter<false>(bufs[0], (const float4*)x + (line0 << 4), 0, nv, lane);
    }

    for (long b = gwarp; b < n_batches; b += nwarp) {
        const long line0 = b << 5;
        const float4* gin  = (const float4*)x   + (line0 << 4);
        float4*       gout = (float4*)out       + (line0 << 4);
        long nv_l = n_lines - line0;
        const int nvalid = (nv_l >= 32) ? 32 : (int)nv_l;
        const bool full = (nvalid == 32);

        #pragma unroll
        for (int h = 0; h < 4; h++) {
            // issue next quarter into the other buffer, then wait for current
            if (h < 3) {
                if (full) issue_quarter<true >(bufs[cur ^ 1], gin, h + 1, 32,     lane);
                else      issue_quarter<false>(bufs[cur ^ 1], gin, h + 1, nvalid, lane);
                asm volatile("cp.async.wait_group 1;");
            } else {
                const long bn = b + nwarp;
                if (bn < n_batches) {
                    const long l0n = bn << 5;
                    long nvn_l = n_lines - l0n;
                    const int nvn = (nvn_l >= 32) ? 32 : (int)nvn_l;
                    if (nvn == 32)
                        issue_quarter<true >(bufs[cur ^ 1],
                                             (const float4*)x + (l0n << 4), 0, 32, lane);
                    else
                        issue_quarter<false>(bufs[cur ^ 1],
                                             (const float4*)x + (l0n << 4), 0, nvn, lane);
                    asm volatile("cp.async.wait_group 1;");
                } else {
                    asm volatile("cp.async.wait_group 0;");
                }
            }
            __syncwarp();

            if (full)
                process_and_flush<true >(vals, bufs[cur], gout, h, 32,     lane, lsw2);
            else
                process_and_flush<false>(vals, bufs[cur], gout, h, nvalid, lane, lsw2);

            cur ^= 1;
        }

        // bulk cleanup: wipe table to sentinel (coalesced STS.128)
        {
            uint4* vp = (uint4*)vals;
            #pragma unroll
            for (int j = 0; j < 16; j++) vp[j * 32 + lane] = sent4;
        }
        __syncwarp();
    }
}

extern "C" void kernel_launch(void* const* d_in, const int* in_sizes, int n_in,
                              void* d_out, int out_size)
{
    (void)n_in; (void)out_size;
    const float* x = (const float*)d_in[0];
    float* out = (float*)d_out;
    const long n = (long)in_sizes[0];

    cudaFuncSetAttribute(cluster_kernel,
                         cudaFuncAttributeMaxDynamicSharedMemorySize, SMEM_TOTAL);

    cluster_kernel<<<148, THREADS, SMEM_TOTAL>>>(x, out, n);
}